// round 1
// baseline (speedup 1.0000x reference)
#include <cuda_runtime.h>
#include <cuda_fp16.h>
#include <cstdint>

#define HID       128
#define KTYPES    8
#define CH        2048       // edges per block
#define NTHREADS  256
#define GROUP     64         // edges per MMA group
#define MST       136        // smem stride (halves) for M tile  (128 + 8 pad)
#define WST       136        // smem stride (halves) for W tile

// dynamic smem layout (bytes):
//  M_s : 128*MST*2      = 34816
//  W_s :  64*WST*2      = 17408
//  bin : CH * 2         = 4096
//  cnt/off/pos : 3*8*4  = 96
#define SMEM_M_OFF   0
#define SMEM_W_OFF   (128*MST*2)
#define SMEM_BIN_OFF (SMEM_W_OFF + 64*WST*2)
#define SMEM_CNT_OFF (SMEM_BIN_OFF + CH*2)
#define SMEM_BYTES   (SMEM_CNT_OFF + 3*8*4)

__device__ __forceinline__ uint32_t smem_u32(const void* p) {
    return (uint32_t)__cvta_generic_to_shared(p);
}

extern "C" __global__ void __launch_bounds__(NTHREADS)
matmsg_kernel(const float* __restrict__ hw,
              const float* __restrict__ ef,
              const float* __restrict__ em,
              float* __restrict__ out, int E)
{
    extern __shared__ char smem[];
    half*     M_s   = (half*)(smem + SMEM_M_OFF);     // [128][MST]
    half*     W_s   = (half*)(smem + SMEM_W_OFF);     // [64][WST]
    uint16_t* bin   = (uint16_t*)(smem + SMEM_BIN_OFF);
    int*      s_cnt = (int*)(smem + SMEM_CNT_OFF);
    int*      s_off = s_cnt + 8;
    int*      s_pos = s_off + 8;

    const int tid  = threadIdx.x;
    const int base = blockIdx.x * CH;
    const int nloc = min(CH, E - base);

    if (tid < 8) s_cnt[tid] = 0;
    __syncthreads();

    // ---- Phase 1: per-edge type (argmax of one-hot) + histogram ----
    int ty[CH / NTHREADS];
#pragma unroll
    for (int i = 0; i < CH / NTHREADS; i++) {
        const int l = tid + i * NTHREADS;
        int t = 0;
        if (l < nloc) {
            const float4* fp = (const float4*)(ef + (size_t)(base + l) * KTYPES);
            float4 f0 = fp[0], f1 = fp[1];
            if (f0.y > 0.5f) t = 1;
            if (f0.z > 0.5f) t = 2;
            if (f0.w > 0.5f) t = 3;
            if (f1.x > 0.5f) t = 4;
            if (f1.y > 0.5f) t = 5;
            if (f1.z > 0.5f) t = 6;
            if (f1.w > 0.5f) t = 7;
            atomicAdd(&s_cnt[t], 1);
        }
        ty[i] = t;
    }
    __syncthreads();

    if (tid == 0) {
        int acc = 0;
#pragma unroll
        for (int k = 0; k < KTYPES; k++) {
            s_off[k] = acc; s_pos[k] = acc; acc += s_cnt[k];
        }
    }
    __syncthreads();

    // ---- Phase 2: scatter local indices into per-type bins ----
#pragma unroll
    for (int i = 0; i < CH / NTHREADS; i++) {
        const int l = tid + i * NTHREADS;
        if (l < nloc) {
            int p = atomicAdd(&s_pos[ty[i]], 1);
            bin[p] = (uint16_t)l;
        }
    }
    __syncthreads();

    const int warp = tid >> 5;
    const int lane = tid & 31;

    // ---- Phase 3: per-type gather + HMMA ----
    for (int k = 0; k < KTYPES; k++) {
        const int nk  = s_cnt[k];
        if (nk == 0) continue;
        const int off = s_off[k];

        __syncthreads();  // guard M_s against previous k's reads
        // load M_k (128x128 fp32) -> fp16 smem, row-major [h][d]
        {
            const float4* mp = (const float4*)(em + (size_t)k * HID * HID);
#pragma unroll
            for (int i = 0; i < (HID * HID / 4) / NTHREADS; i++) {  // 16 iters
                const int idx = tid + i * NTHREADS;   // float4 index
                const int row = idx >> 5;             // 32 float4 per row
                const int c4  = idx & 31;
                float4 v = mp[idx];
                half2* dst = (half2*)&M_s[row * MST + c4 * 4];
                dst[0] = __floats2half2_rn(v.x, v.y);
                dst[1] = __floats2half2_rn(v.z, v.w);
            }
        }
        __syncthreads();

        const int ngr = (nk + GROUP - 1) / GROUP;
        for (int g = 0; g < ngr; g++) {
            __syncthreads();  // guard W_s reuse

            // gather GROUP h_w rows -> fp16 smem tile [64][WST]
            {
                const int r  = tid >> 2;            // 0..63
                const int q  = tid & 3;             // quarter of the row
                const int gr = g * GROUP + r;
                half2* dst = (half2*)&W_s[r * WST + q * 32];
                if (gr < nk) {
                    const int eg = base + bin[off + gr];
                    const float4* wp = (const float4*)(hw + (size_t)eg * HID) + q * 8;
#pragma unroll
                    for (int j = 0; j < 8; j++) {
                        float4 v = wp[j];
                        dst[2 * j]     = __floats2half2_rn(v.x, v.y);
                        dst[2 * j + 1] = __floats2half2_rn(v.z, v.w);
                    }
                } else {
                    const half2 z = __floats2half2_rn(0.f, 0.f);
#pragma unroll
                    for (int j = 0; j < 16; j++) dst[j] = z;
                }
            }
            __syncthreads();

            // warp w computes h columns [16w, 16w+16) for all 64 group edges
            float c[4][2][4];
#pragma unroll
            for (int et = 0; et < 4; et++)
#pragma unroll
                for (int ht = 0; ht < 2; ht++)
#pragma unroll
                    for (int j = 0; j < 4; j++) c[et][ht][j] = 0.f;

#pragma unroll
            for (int ks = 0; ks < 8; ks++) {
                uint32_t b0[2], b1[2];
#pragma unroll
                for (int ht = 0; ht < 2; ht++) {
                    const int nrow = warp * 16 + ht * 8 + (lane & 7);
                    const int kcol = ks * 16 + ((lane >> 3) & 1) * 8;
                    uint32_t addr = smem_u32(&M_s[nrow * MST + kcol]);
                    asm volatile("ldmatrix.sync.aligned.m8n8.x2.shared.b16 {%0,%1}, [%2];"
                                 : "=r"(b0[ht]), "=r"(b1[ht]) : "r"(addr));
                }
#pragma unroll
                for (int et = 0; et < 4; et++) {
                    const int arow = et * 16 + (lane & 15);
                    const int acol = ks * 16 + (lane >> 4) * 8;
                    uint32_t addr = smem_u32(&W_s[arow * WST + acol]);
                    uint32_t a0, a1, a2, a3;
                    asm volatile("ldmatrix.sync.aligned.m8n8.x4.shared.b16 {%0,%1,%2,%3}, [%4];"
                                 : "=r"(a0), "=r"(a1), "=r"(a2), "=r"(a3) : "r"(addr));
#pragma unroll
                    for (int ht = 0; ht < 2; ht++) {
                        asm volatile(
                            "mma.sync.aligned.m16n8k16.row.col.f32.f16.f16.f32 "
                            "{%0,%1,%2,%3}, {%4,%5,%6,%7}, {%8,%9}, {%0,%1,%2,%3};"
                            : "+f"(c[et][ht][0]), "+f"(c[et][ht][1]),
                              "+f"(c[et][ht][2]), "+f"(c[et][ht][3])
                            : "r"(a0), "r"(a1), "r"(a2), "r"(a3),
                              "r"(b0[ht]), "r"(b1[ht]));
                    }
                }
            }

            // epilogue: scatter to out[edge][h]
#pragma unroll
            for (int et = 0; et < 4; et++) {
                const int r0 = et * 16 + (lane >> 2);
#pragma unroll
                for (int hf = 0; hf < 2; hf++) {
                    const int r  = r0 + hf * 8;
                    const int gr = g * GROUP + r;
                    if (gr < nk) {
                        const int eg = base + bin[off + gr];
                        float* orow = out + (size_t)eg * HID + warp * 16 + (lane & 3) * 2;
#pragma unroll
                        for (int ht = 0; ht < 2; ht++) {
                            float2 v = make_float2(c[et][ht][hf * 2], c[et][ht][hf * 2 + 1]);
                            *(float2*)(orow + ht * 8) = v;
                        }
                    }
                }
            }
        } // groups
    } // k
}

extern "C" void kernel_launch(void* const* d_in, const int* in_sizes, int n_in,
                              void* d_out, int out_size) {
    // inputs (metadata order): h_v (unused), h_w, edge_features, edge_matrices
    const float* hw = (const float*)d_in[1];
    const float* ef = (const float*)d_in[2];
    const float* em = (const float*)d_in[3];
    float* out = (float*)d_out;
    const int E = in_sizes[1] / HID;
    const int grid = (E + CH - 1) / CH;

    cudaFuncSetAttribute(matmsg_kernel,
                         cudaFuncAttributeMaxDynamicSharedMemorySize, SMEM_BYTES);
    matmsg_kernel<<<grid, NTHREADS, SMEM_BYTES>>>(hw, ef, em, out, E);
}

// round 2
// speedup vs baseline: 1.2749x; 1.2749x over previous
#include <cuda_runtime.h>
#include <cuda_fp16.h>
#include <cstdint>

#define HID       128
#define KTYPES    8
#define CH        1024       // edges per block (smaller -> 313 CTAs -> 2/SM)
#define NTHREADS  256
#define GROUP     64         // edges per MMA group
#define MST       136        // smem stride (halves) for M tile  (128 + 8 pad)
#define WST       136        // smem stride (halves) for W tile

// dynamic smem layout (bytes):
//  M_s : 128*MST*2        = 34816
//  W_s : 2 * 64*WST*2     = 34816   (double buffered)
//  bin : CH * 2           = 2048
//  cnt/off/pos : 3*8*4    = 96
#define SMEM_M_OFF   0
#define SMEM_W_OFF   (128*MST*2)
#define SMEM_BIN_OFF (SMEM_W_OFF + 2*64*WST*2)
#define SMEM_CNT_OFF (SMEM_BIN_OFF + CH*2)
#define SMEM_BYTES   (SMEM_CNT_OFF + 3*8*4)

__device__ __forceinline__ uint32_t smem_u32(const void* p) {
    return (uint32_t)__cvta_generic_to_shared(p);
}

extern "C" __global__ void __launch_bounds__(NTHREADS, 2)
matmsg_kernel(const float* __restrict__ hw,
              const float* __restrict__ ef,
              const float* __restrict__ em,
              float* __restrict__ out, int E)
{
    extern __shared__ char smem[];
    half*     M_s   = (half*)(smem + SMEM_M_OFF);     // [128][MST]
    half*     W_s   = (half*)(smem + SMEM_W_OFF);     // [2][64][WST]
    uint16_t* bin   = (uint16_t*)(smem + SMEM_BIN_OFF);
    int*      s_cnt = (int*)(smem + SMEM_CNT_OFF);
    int*      s_off = s_cnt + 8;
    int*      s_pos = s_off + 8;

    const int tid  = threadIdx.x;
    const int base = blockIdx.x * CH;
    const int nloc = min(CH, E - base);

    if (tid < 8) s_cnt[tid] = 0;
    __syncthreads();

    // ---- Phase 1: per-edge type (argmax of one-hot) + histogram ----
    int ty[CH / NTHREADS];
#pragma unroll
    for (int i = 0; i < CH / NTHREADS; i++) {
        const int l = tid + i * NTHREADS;
        int t = 0;
        if (l < nloc) {
            const float4* fp = (const float4*)(ef + (size_t)(base + l) * KTYPES);
            float4 f0 = fp[0], f1 = fp[1];
            if (f0.y > 0.5f) t = 1;
            if (f0.z > 0.5f) t = 2;
            if (f0.w > 0.5f) t = 3;
            if (f1.x > 0.5f) t = 4;
            if (f1.y > 0.5f) t = 5;
            if (f1.z > 0.5f) t = 6;
            if (f1.w > 0.5f) t = 7;
            atomicAdd(&s_cnt[t], 1);
        }
        ty[i] = t;
    }
    __syncthreads();

    if (tid == 0) {
        int acc = 0;
#pragma unroll
        for (int k = 0; k < KTYPES; k++) {
            s_off[k] = acc; s_pos[k] = acc; acc += s_cnt[k];
        }
    }
    __syncthreads();

    // ---- Phase 2: scatter local indices into per-type bins ----
#pragma unroll
    for (int i = 0; i < CH / NTHREADS; i++) {
        const int l = tid + i * NTHREADS;
        if (l < nloc) {
            int p = atomicAdd(&s_pos[ty[i]], 1);
            bin[p] = (uint16_t)l;
        }
    }
    __syncthreads();

    const int warp = tid >> 5;
    const int lane = tid & 31;
    const int gr_r = tid >> 2;   // row within group this thread gathers (0..63)
    const int gr_q = tid & 3;    // quarter of the row

    float4 pf[8];                // register prefetch buffer (one h_w row quarter)

    // ---- Phase 3: per-type gather (pipelined) + HMMA ----
    for (int k = 0; k < KTYPES; k++) {
        const int nk  = s_cnt[k];
        if (nk == 0) continue;
        const int off = s_off[k];

        __syncthreads();  // all MMA reads of M_s from previous k done
        // load M_k (128x128 fp32) -> fp16 smem, row-major [h][d]
        {
            const float4* mp = (const float4*)(em + (size_t)k * HID * HID);
#pragma unroll
            for (int i = 0; i < (HID * HID / 4) / NTHREADS; i++) {  // 16 iters
                const int idx = tid + i * NTHREADS;   // float4 index
                const int row = idx >> 5;             // 32 float4 per row
                const int c4  = idx & 31;
                float4 v = mp[idx];
                half2* dst = (half2*)&M_s[row * MST + c4 * 4];
                dst[0] = __floats2half2_rn(v.x, v.y);
                dst[1] = __floats2half2_rn(v.z, v.w);
            }
        }

        const int ngr = (nk + GROUP - 1) / GROUP;

        // -- pipeline prologue --
        // LDG group 0
        {
            const int gr = gr_r;  // g=0
            if (gr < nk) {
                const int eg = base + bin[off + gr];
                const float4* wp = (const float4*)(hw + (size_t)eg * HID) + gr_q * 8;
#pragma unroll
                for (int j = 0; j < 8; j++) pf[j] = wp[j];
            }
        }
        // convert + STS group 0 -> buf 0
        {
            half2* dst = (half2*)&W_s[0 * 64 * WST + gr_r * WST + gr_q * 32];
            if (gr_r < nk) {
#pragma unroll
                for (int j = 0; j < 8; j++) {
                    dst[2 * j]     = __floats2half2_rn(pf[j].x, pf[j].y);
                    dst[2 * j + 1] = __floats2half2_rn(pf[j].z, pf[j].w);
                }
            } else {
                const half2 z = __floats2half2_rn(0.f, 0.f);
#pragma unroll
                for (int j = 0; j < 16; j++) dst[j] = z;
            }
        }
        // LDG group 1
        if (ngr > 1) {
            const int gr = GROUP + gr_r;
            if (gr < nk) {
                const int eg = base + bin[off + gr];
                const float4* wp = (const float4*)(hw + (size_t)eg * HID) + gr_q * 8;
#pragma unroll
                for (int j = 0; j < 8; j++) pf[j] = wp[j];
            }
        }
        __syncthreads();  // M_s + W_s buf0 ready

        for (int g = 0; g < ngr; g++) {
            const half* Wb = &W_s[(g & 1) * 64 * WST];

            // ---- MMA on group g ----
            float c[4][2][4];
#pragma unroll
            for (int et = 0; et < 4; et++)
#pragma unroll
                for (int ht = 0; ht < 2; ht++)
#pragma unroll
                    for (int j = 0; j < 4; j++) c[et][ht][j] = 0.f;

#pragma unroll
            for (int ks = 0; ks < 8; ks++) {
                uint32_t b0[2], b1[2];
#pragma unroll
                for (int ht = 0; ht < 2; ht++) {
                    const int nrow = warp * 16 + ht * 8 + (lane & 7);
                    const int kcol = ks * 16 + ((lane >> 3) & 1) * 8;
                    uint32_t addr = smem_u32(&M_s[nrow * MST + kcol]);
                    asm volatile("ldmatrix.sync.aligned.m8n8.x2.shared.b16 {%0,%1}, [%2];"
                                 : "=r"(b0[ht]), "=r"(b1[ht]) : "r"(addr));
                }
#pragma unroll
                for (int et = 0; et < 4; et++) {
                    const int arow = et * 16 + (lane & 15);
                    const int acol = ks * 16 + (lane >> 4) * 8;
                    uint32_t addr = smem_u32(&Wb[arow * WST + acol]);
                    uint32_t a0, a1, a2, a3;
                    asm volatile("ldmatrix.sync.aligned.m8n8.x4.shared.b16 {%0,%1,%2,%3}, [%4];"
                                 : "=r"(a0), "=r"(a1), "=r"(a2), "=r"(a3) : "r"(addr));
#pragma unroll
                    for (int ht = 0; ht < 2; ht++) {
                        asm volatile(
                            "mma.sync.aligned.m16n8k16.row.col.f32.f16.f16.f32 "
                            "{%0,%1,%2,%3}, {%4,%5,%6,%7}, {%8,%9}, {%0,%1,%2,%3};"
                            : "+f"(c[et][ht][0]), "+f"(c[et][ht][1]),
                              "+f"(c[et][ht][2]), "+f"(c[et][ht][3])
                            : "r"(a0), "r"(a1), "r"(a2), "r"(a3),
                              "r"(b0[ht]), "r"(b1[ht]));
                    }
                }
            }

            // epilogue: scatter to out[edge][h]
#pragma unroll
            for (int et = 0; et < 4; et++) {
                const int r0 = et * 16 + (lane >> 2);
#pragma unroll
                for (int hf = 0; hf < 2; hf++) {
                    const int r  = r0 + hf * 8;
                    const int gr = g * GROUP + r;
                    if (gr < nk) {
                        const int eg = base + bin[off + gr];
                        float* orow = out + (size_t)eg * HID + warp * 16 + (lane & 3) * 2;
#pragma unroll
                        for (int ht = 0; ht < 2; ht++) {
                            float2 v = make_float2(c[et][ht][hf * 2], c[et][ht][hf * 2 + 1]);
                            *(float2*)(orow + ht * 8) = v;
                        }
                    }
                }
            }

            // ---- feed pipeline: STS group g+1 (loaded), LDG group g+2 ----
            if (g + 1 < ngr) {
                const int gr1 = (g + 1) * GROUP + gr_r;
                half2* dst = (half2*)&W_s[((g + 1) & 1) * 64 * WST + gr_r * WST + gr_q * 32];
                if (gr1 < nk) {
#pragma unroll
                    for (int j = 0; j < 8; j++) {
                        dst[2 * j]     = __floats2half2_rn(pf[j].x, pf[j].y);
                        dst[2 * j + 1] = __floats2half2_rn(pf[j].z, pf[j].w);
                    }
                } else {
                    const half2 z = __floats2half2_rn(0.f, 0.f);
#pragma unroll
                    for (int j = 0; j < 16; j++) dst[j] = z;
                }
                if (g + 2 < ngr) {
                    const int gr2 = (g + 2) * GROUP + gr_r;
                    if (gr2 < nk) {
                        const int eg = base + bin[off + gr2];
                        const float4* wp = (const float4*)(hw + (size_t)eg * HID) + gr_q * 8;
#pragma unroll
                        for (int j = 0; j < 8; j++) pf[j] = wp[j];
                    }
                }
                __syncthreads();  // STS(g+1) visible; MMA(g) done for all warps
            }
        } // groups
    } // k
}

extern "C" void kernel_launch(void* const* d_in, const int* in_sizes, int n_in,
                              void* d_out, int out_size) {
    // inputs (metadata order): h_v (unused), h_w, edge_features, edge_matrices
    const float* hw = (const float*)d_in[1];
    const float* ef = (const float*)d_in[2];
    const float* em = (const float*)d_in[3];
    float* out = (float*)d_out;
    const int E = in_sizes[1] / HID;
    const int grid = (E + CH - 1) / CH;

    cudaFuncSetAttribute(matmsg_kernel,
                         cudaFuncAttributeMaxDynamicSharedMemorySize, SMEM_BYTES);
    matmsg_kernel<<<grid, NTHREADS, SMEM_BYTES>>>(hw, ef, em, out, E);
}

// round 5
// speedup vs baseline: 1.9481x; 1.5280x over previous
#include <cuda_runtime.h>
#include <cuda_fp16.h>
#include <cstdint>

#define HID       128
#define KTYPES    8
#define CH        768        // edges per block -> grid 417 -> ~2.8 CTA/SM
#define NTHREADS  256
#define GROUP     32         // edges per MMA group
#define MST       136        // smem stride (halves) for M tile  (128 + 8 pad)
#define WST       136        // smem stride (halves) for W tile

// dynamic smem layout (bytes):
//  M_s : 128*MST*2        = 34816
//  W_s : 2 * 32*WST*2     = 17408   (double buffered)
//  bin : CH * 2           = 1536
//  cnt/off/pos : 3*8*4    = 96
#define SMEM_M_OFF   0
#define SMEM_W_OFF   (128*MST*2)
#define SMEM_BIN_OFF (SMEM_W_OFF + 2*GROUP*WST*2)
#define SMEM_CNT_OFF (SMEM_BIN_OFF + CH*2)
#define SMEM_BYTES   (SMEM_CNT_OFF + 3*8*4)

__device__ __forceinline__ uint32_t smem_u32(const void* p) {
    return (uint32_t)__cvta_generic_to_shared(p);
}

extern "C" __global__ void __launch_bounds__(NTHREADS, 3)
matmsg_kernel(const float* __restrict__ hw,
              const float* __restrict__ ef,
              const float* __restrict__ em,
              float* __restrict__ out, int E)
{
    extern __shared__ char smem[];
    half*     M_s   = (half*)(smem + SMEM_M_OFF);     // [128][MST]
    half*     W_s   = (half*)(smem + SMEM_W_OFF);     // [2][32][WST]
    uint16_t* bin   = (uint16_t*)(smem + SMEM_BIN_OFF);
    int*      s_cnt = (int*)(smem + SMEM_CNT_OFF);
    int*      s_off = s_cnt + 8;
    int*      s_pos = s_off + 8;

    const int tid  = threadIdx.x;
    const int base = blockIdx.x * CH;
    const int nloc = min(CH, E - base);

    if (tid < 8) s_cnt[tid] = 0;
    __syncthreads();

    // ---- Phase 1: per-edge type (argmax of one-hot) + histogram ----
    int ty[CH / NTHREADS];
#pragma unroll
    for (int i = 0; i < CH / NTHREADS; i++) {
        const int l = tid + i * NTHREADS;
        int t = 0;
        if (l < nloc) {
            const float4* fp = (const float4*)(ef + (size_t)(base + l) * KTYPES);
            float4 f0 = fp[0], f1 = fp[1];
            if (f0.y > 0.5f) t = 1;
            if (f0.z > 0.5f) t = 2;
            if (f0.w > 0.5f) t = 3;
            if (f1.x > 0.5f) t = 4;
            if (f1.y > 0.5f) t = 5;
            if (f1.z > 0.5f) t = 6;
            if (f1.w > 0.5f) t = 7;
            atomicAdd(&s_cnt[t], 1);
        }
        ty[i] = t;
    }
    __syncthreads();

    if (tid == 0) {
        int acc = 0;
#pragma unroll
        for (int k = 0; k < KTYPES; k++) {
            s_off[k] = acc; s_pos[k] = acc; acc += s_cnt[k];
        }
    }
    __syncthreads();

    // ---- Phase 2: scatter local indices into per-type bins ----
#pragma unroll
    for (int i = 0; i < CH / NTHREADS; i++) {
        const int l = tid + i * NTHREADS;
        if (l < nloc) {
            int p = atomicAdd(&s_pos[ty[i]], 1);
            bin[p] = (uint16_t)l;
        }
    }
    __syncthreads();

    const int warp = tid >> 5;
    const int lane = tid & 31;
    const int gr_r = tid >> 3;   // row within group this thread gathers (0..31)
    const int gr_q = tid & 7;    // eighth of the row (16 floats)

    float4 pf[4];                // register prefetch buffer (row eighth)

    // ---- Phase 3: per-type gather (pipelined) + HMMA ----
    for (int k = 0; k < KTYPES; k++) {
        const int nk  = s_cnt[k];
        if (nk == 0) continue;
        const int off = s_off[k];

        __syncthreads();  // all MMA/frag reads of previous k done
        // stage M_k (128x128 fp32) -> fp16 smem, row-major [h][d]
        {
            const float4* mp = (const float4*)(em + (size_t)k * HID * HID);
#pragma unroll
            for (int i = 0; i < (HID * HID / 4) / NTHREADS; i++) {  // 16 iters
                const int idx = tid + i * NTHREADS;   // float4 index
                const int row = idx >> 5;             // 32 float4 per row
                const int c4  = idx & 31;
                float4 v = mp[idx];
                half2* dst = (half2*)&M_s[row * MST + c4 * 4];
                dst[0] = __floats2half2_rn(v.x, v.y);
                dst[1] = __floats2half2_rn(v.z, v.w);
            }
        }

        const int ngr = (nk + GROUP - 1) / GROUP;

        // -- pipeline prologue --
        // LDG group 0
        if (gr_r < nk) {
            const int eg = base + bin[off + gr_r];
            const float4* wp = (const float4*)(hw + (size_t)eg * HID) + gr_q * 4;
#pragma unroll
            for (int j = 0; j < 4; j++) pf[j] = wp[j];
        }
        // convert + STS group 0 -> buf 0
        {
            half2* dst = (half2*)&W_s[gr_r * WST + gr_q * 16];
            if (gr_r < nk) {
#pragma unroll
                for (int j = 0; j < 4; j++) {
                    dst[2 * j]     = __floats2half2_rn(pf[j].x, pf[j].y);
                    dst[2 * j + 1] = __floats2half2_rn(pf[j].z, pf[j].w);
                }
            } else {
                const half2 z = __floats2half2_rn(0.f, 0.f);
#pragma unroll
                for (int j = 0; j < 8; j++) dst[j] = z;
            }
        }
        // LDG group 1
        if (ngr > 1) {
            const int gr = GROUP + gr_r;
            if (gr < nk) {
                const int eg = base + bin[off + gr];
                const float4* wp = (const float4*)(hw + (size_t)eg * HID) + gr_q * 4;
#pragma unroll
                for (int j = 0; j < 4; j++) pf[j] = wp[j];
            }
        }
        __syncthreads();  // M_s + W_s buf0 ready

        // hoist M_k fragments for this warp's 16 hid columns (constant per type)
        uint32_t bfr[8][2][2];
#pragma unroll
        for (int ks = 0; ks < 8; ks++) {
#pragma unroll
            for (int ht = 0; ht < 2; ht++) {
                const int nrow = warp * 16 + ht * 8 + (lane & 7);
                const int kcol = ks * 16 + ((lane >> 3) & 1) * 8;
                uint32_t addr = smem_u32(&M_s[nrow * MST + kcol]);
                asm volatile("ldmatrix.sync.aligned.m8n8.x2.shared.b16 {%0,%1}, [%2];"
                             : "=r"(bfr[ks][ht][0]), "=r"(bfr[ks][ht][1]) : "r"(addr));
            }
        }

        for (int g = 0; g < ngr; g++) {
            const half* Wb = &W_s[(g & 1) * GROUP * WST];

            // ---- MMA on group g ----
            float c[2][2][4];
#pragma unroll
            for (int et = 0; et < 2; et++)
#pragma unroll
                for (int ht = 0; ht < 2; ht++)
#pragma unroll
                    for (int j = 0; j < 4; j++) c[et][ht][j] = 0.f;

#pragma unroll
            for (int ks = 0; ks < 8; ks++) {
#pragma unroll
                for (int et = 0; et < 2; et++) {
                    const int arow = et * 16 + (lane & 15);
                    const int acol = ks * 16 + (lane >> 4) * 8;
                    uint32_t addr = smem_u32(&Wb[arow * WST + acol]);
                    uint32_t a0, a1, a2, a3;
                    asm volatile("ldmatrix.sync.aligned.m8n8.x4.shared.b16 {%0,%1,%2,%3}, [%4];"
                                 : "=r"(a0), "=r"(a1), "=r"(a2), "=r"(a3) : "r"(addr));
#pragma unroll
                    for (int ht = 0; ht < 2; ht++) {
                        asm volatile(
                            "mma.sync.aligned.m16n8k16.row.col.f32.f16.f16.f32 "
                            "{%0,%1,%2,%3}, {%4,%5,%6,%7}, {%8,%9}, {%0,%1,%2,%3};"
                            : "+f"(c[et][ht][0]), "+f"(c[et][ht][1]),
                              "+f"(c[et][ht][2]), "+f"(c[et][ht][3])
                            : "r"(a0), "r"(a1), "r"(a2), "r"(a3),
                              "r"(bfr[ks][ht][0]), "r"(bfr[ks][ht][1]));
                    }
                }
            }

            // epilogue: scatter to out[edge][h]
#pragma unroll
            for (int et = 0; et < 2; et++) {
                const int r0 = et * 16 + (lane >> 2);
#pragma unroll
                for (int hf = 0; hf < 2; hf++) {
                    const int r  = r0 + hf * 8;
                    const int gr = g * GROUP + r;
                    if (gr < nk) {
                        const int eg = base + bin[off + gr];
                        float* orow = out + (size_t)eg * HID + warp * 16 + (lane & 3) * 2;
#pragma unroll
                        for (int ht = 0; ht < 2; ht++) {
                            float2 v = make_float2(c[et][ht][hf * 2], c[et][ht][hf * 2 + 1]);
                            *(float2*)(orow + ht * 8) = v;
                        }
                    }
                }
            }

            // ---- feed pipeline: STS group g+1 (loaded), LDG group g+2 ----
            if (g + 1 < ngr) {
                const int gr1 = (g + 1) * GROUP + gr_r;
                half2* dst = (half2*)&W_s[((g + 1) & 1) * GROUP * WST + gr_r * WST + gr_q * 16];
                if (gr1 < nk) {
#pragma unroll
                    for (int j = 0; j < 4; j++) {
                        dst[2 * j]     = __floats2half2_rn(pf[j].x, pf[j].y);
                        dst[2 * j + 1] = __floats2half2_rn(pf[j].z, pf[j].w);
                    }
                } else {
                    const half2 z = __floats2half2_rn(0.f, 0.f);
#pragma unroll
                    for (int j = 0; j < 8; j++) dst[j] = z;
                }
                if (g + 2 < ngr) {
                    const int gr2 = (g + 2) * GROUP + gr_r;
                    if (gr2 < nk) {
                        const int eg = base + bin[off + gr2];
                        const float4* wp = (const float4*)(hw + (size_t)eg * HID) + gr_q * 4;
#pragma unroll
                        for (int j = 0; j < 4; j++) pf[j] = wp[j];
                    }
                }
                __syncthreads();  // STS(g+1) visible; MMA(g) done for all warps
            }
        } // groups
    } // k
}

extern "C" void kernel_launch(void* const* d_in, const int* in_sizes, int n_in,
                              void* d_out, int out_size) {
    // inputs (metadata order): h_v (unused), h_w, edge_features, edge_matrices
    const float* hw = (const float*)d_in[1];
    const float* ef = (const float*)d_in[2];
    const float* em = (const float*)d_in[3];
    float* out = (float*)d_out;
    const int E = in_sizes[1] / HID;
    const int grid = (E + CH - 1) / CH;

    cudaFuncSetAttribute(matmsg_kernel,
                         cudaFuncAttributeMaxDynamicSharedMemorySize, SMEM_BYTES);
    matmsg_kernel<<<grid, NTHREADS, SMEM_BYTES>>>(hw, ef, em, out, E);
}